// round 9
// baseline (speedup 1.0000x reference)
#include <cuda_runtime.h>
#include <stdint.h>

// Hash-grid trilinear interpolation — two-pass table slicing, (pt,half) x U=2.
//
// DRAM: pass P gathers only corners in table slice P (top vid bit, 64MB/slice);
// slice fits L2 during its pass so bucket reuse is captured by LRU (R6/R7).
// Pass 0 writes partial sums to out, pass 1 adds and finalizes. Pass 1 runs in
// REVERSED point order so pass 0's tail partial-sum lines are L2 hits.
//
// L1: thread = (point-pair, 16B half). Corner pairs (2p,2p+1) are adjacent
// buckets -> a thread's two loads are 32B apart (same 128B line, L1 hit).
// U=2 points/thread: ~8 active gathers in flight, 2x instructions per stall
// (R7 was duty-limited at issue=37%).

#define BUCKETS_MASK ((1u << 22) - 1u)
#define SLICE_SHIFT 21
#define P1 1u
#define P2 2654435761u
#define P3 805459861u

__device__ __forceinline__ void weights_and_hash(
    const float* __restrict__ pts, int pt,
    uint32_t& h, float* w)
{
    float x = pts[3 * pt + 0];
    float y = pts[3 * pt + 1];
    float z = pts[3 * pt + 2];
    float qx = x * 1024.0f, qy = y * 1024.0f, qz = z * 1024.0f;
    float bxf = floorf(qx), byf = floorf(qy), bzf = floorf(qz);
    float fx = qx - bxf, fy = qy - byf, fz = qz - bzf;
    uint32_t bx = (uint32_t)(int)bxf;
    uint32_t by = (uint32_t)(int)byf;
    uint32_t bz = (uint32_t)(int)bzf;
    h = bx * P1 + by * P2 + bz * P3;
    float gx = 1.0f - fx, gy = 1.0f - fy, gz = 1.0f - fz;
    w[0] = gx * gy * gz;  w[1] = fx * gy * gz;
    w[2] = gx * fy * gz;  w[3] = fx * fy * gz;
    w[4] = gx * gy * fz;  w[5] = fx * gy * fz;
    w[6] = gx * fy * fz;  w[7] = fx * fy * fz;
}

template <int PASS>
__global__ void hashgrid_u2_kernel(
    const float* __restrict__ pts,   // (N,3)
    const char*  __restrict__ vf,    // (BUCKETS, 8 fp32) = 32 B per bucket
    float4*      __restrict__ out,   // (N, 8 fp32) = 2 float4 per point
    int n, int n_threads)
{
    int s = blockIdx.x * blockDim.x + threadIdx.x;
    if (s >= n_threads) return;
    if (PASS == 1) s = n_threads - 1 - s;   // reversed order: catch pass-0 tail in L2

    int pairi = s >> 1;
    int half  = s & 1;
    int p0 = 2 * pairi;
    int p1 = p0 + 1;
    bool v1 = (p1 < n);
    if (p0 >= n) return;

    uint32_t h0, h1;
    float w0[8], w1[8];
    weights_and_hash(pts, p0, h0, w0);
    weights_and_hash(pts, v1 ? p1 : p0, h1, w1);

    const uint32_t hoff[8] = {0u, P1, P2, P1 + P2, P3, P1 + P3, P2 + P3, P1 + P2 + P3};
    const char* base = vf + ((uint32_t)half << 4);

    // Issue all predicated gathers for both points first (~8 active in flight).
    float4 f0[8], f1[8];
#pragma unroll
    for (int c = 0; c < 8; c++) {
        uint32_t vid = (h0 + hoff[c]) & BUCKETS_MASK;
        f0[c] = make_float4(0.f, 0.f, 0.f, 0.f);
        if ((vid >> SLICE_SHIFT) == (uint32_t)PASS)
            f0[c] = __ldg((const float4*)(base + ((size_t)vid << 5)));
    }
#pragma unroll
    for (int c = 0; c < 8; c++) {
        uint32_t vid = (h1 + hoff[c]) & BUCKETS_MASK;
        f1[c] = make_float4(0.f, 0.f, 0.f, 0.f);
        if (v1 && ((vid >> SLICE_SHIFT) == (uint32_t)PASS))
            f1[c] = __ldg((const float4*)(base + ((size_t)vid << 5)));
    }

    float4 a0 = make_float4(0.f, 0.f, 0.f, 0.f);
    float4 a1 = make_float4(0.f, 0.f, 0.f, 0.f);
#pragma unroll
    for (int c = 0; c < 8; c++) {
        float wa = w0[c], wb = w1[c];
        a0.x = fmaf(wa, f0[c].x, a0.x);
        a0.y = fmaf(wa, f0[c].y, a0.y);
        a0.z = fmaf(wa, f0[c].z, a0.z);
        a0.w = fmaf(wa, f0[c].w, a0.w);
        a1.x = fmaf(wb, f1[c].x, a1.x);
        a1.y = fmaf(wb, f1[c].y, a1.y);
        a1.z = fmaf(wb, f1[c].z, a1.z);
        a1.w = fmaf(wb, f1[c].w, a1.w);
    }

    float4* op0 = out + 2 * (size_t)p0 + half;
    float4* op1 = out + 2 * (size_t)p1 + half;
    if (PASS == 0) {
        *op0 = a0;
        if (v1) *op1 = a1;
    } else {
        float4 q0 = *op0;
        a0.x += q0.x; a0.y += q0.y; a0.z += q0.z; a0.w += q0.w;
        __stcs(op0, a0);
        if (v1) {
            float4 q1 = *op1;
            a1.x += q1.x; a1.y += q1.y; a1.z += q1.z; a1.w += q1.w;
            __stcs(op1, a1);
        }
    }
}

extern "C" void kernel_launch(void* const* d_in, const int* in_sizes, int n_in,
                              void* d_out, int out_size)
{
    const float* pts = (const float*)d_in[0];
    const char*  vf  = (const char*)d_in[1];
    float4*      out = (float4*)d_out;

    int n = in_sizes[0] / 3;

    int n_pairs = (n + 1) / 2;
    int n_threads = n_pairs * 2;        // one thread per (pair, half)
    int block = 256;
    int grid = (n_threads + block - 1) / block;

    hashgrid_u2_kernel<0><<<grid, block>>>(pts, vf, out, n, n_threads);
    hashgrid_u2_kernel<1><<<grid, block>>>(pts, vf, out, n, n_threads);
}